// round 1
// baseline (speedup 1.0000x reference)
#include <cuda_runtime.h>
#include <math_constants.h>

// NonMaxSuppression: 3x3 max-pool NMS mask on (8,1,2048,2048) fp32.
// out[y][x] = 1.0f iff in[y][x] == max3x3(in, y, x)  (pad -inf)
//             && in[y][x] >= 0.6f
//             && 10 <= y < H-10 && 10 <= x < W-10
//
// Strategy: HBM-bound streaming kernel. Each warp owns a 128-col x 32-row
// strip. Rows are loaded once each as float4 (coalesced 128B per warp),
// horizontal halos come from __shfl + two scalar edge loads, and three
// rows of horizontal maxima roll through registers. Read amplification
// (32+2)/32 ~= 1.06x; no shared memory, no barriers.

#define H 2048
#define W 2048
#define ROWS 32
#define REP_THR 0.6f
#define BORDER 10

__device__ __forceinline__ float4 hmax4(float4 v, float l, float r) {
    float4 h;
    h.x = fmaxf(l,   fmaxf(v.x, v.y));
    h.y = fmaxf(v.x, fmaxf(v.y, v.z));
    h.z = fmaxf(v.y, fmaxf(v.z, v.w));
    h.w = fmaxf(v.z, fmaxf(v.w, r));
    return h;
}

__global__ __launch_bounds__(128, 8)
void nms_kernel(const float* __restrict__ in, float* __restrict__ out) {
    const int lane = threadIdx.x;                 // 0..31
    const int seg  = blockIdx.x * blockDim.y + threadIdx.y;  // 0..15 column segment
    const int b    = blockIdx.z;                  // batch
    const int y0   = blockIdx.y * ROWS;           // first output row of strip

    const int x4 = seg * 128 + lane * 4;          // first of 4 columns

    const float* img = in  + (size_t)b * H * W;
    float*       o   = out + (size_t)b * H * W;

    // --- row loader: float4 of row y (clamped; masked rows never matter) ---
    auto load_row = [&](int y, float4& v, float& l, float& r) {
        int yy = y < 0 ? 0 : (y >= H ? H - 1 : y);
        const float* row = img + (size_t)yy * W;
        v = *reinterpret_cast<const float4*>(row + x4);
        // horizontal halos via shfl within the warp
        float lraw = __shfl_up_sync(0xffffffffu, v.w, 1);
        float rraw = __shfl_down_sync(0xffffffffu, v.x, 1);
        if (lane == 0)
            lraw = (x4 > 0) ? row[x4 - 1] : -CUDART_INF_F;
        if (lane == 31)
            rraw = (x4 + 4 < W) ? row[x4 + 4] : -CUDART_INF_F;
        l = lraw; r = rraw;
    };

    float4 v; float hl, hr;

    load_row(y0 - 1, v, hl, hr);
    float4 hm_m = hmax4(v, hl, hr);     // hmax of row y-1

    float4 v_cur; float l_cur, r_cur;
    load_row(y0, v_cur, l_cur, r_cur);
    float4 hm_c = hmax4(v_cur, l_cur, r_cur);   // hmax of row y

    // column border predicates (constant across rows)
    const bool bx0 = (x4 + 0 >= BORDER) && (x4 + 0 < W - BORDER);
    const bool bx1 = (x4 + 1 >= BORDER) && (x4 + 1 < W - BORDER);
    const bool bx2 = (x4 + 2 >= BORDER) && (x4 + 2 < W - BORDER);
    const bool bx3 = (x4 + 3 >= BORDER) && (x4 + 3 < W - BORDER);

    #pragma unroll 4
    for (int y = y0; y < y0 + ROWS; ++y) {
        float4 v_nxt; float l_nxt, r_nxt;
        load_row(y + 1, v_nxt, l_nxt, r_nxt);
        float4 hm_p = hmax4(v_nxt, l_nxt, r_nxt);  // hmax of row y+1

        const bool by = (y >= BORDER) && (y < H - BORDER);

        float4 res;
        {
            float m;
            m = fmaxf(hm_m.x, fmaxf(hm_c.x, hm_p.x));
            res.x = (by && bx0 && v_cur.x >= REP_THR && v_cur.x == m) ? 1.0f : 0.0f;
            m = fmaxf(hm_m.y, fmaxf(hm_c.y, hm_p.y));
            res.y = (by && bx1 && v_cur.y >= REP_THR && v_cur.y == m) ? 1.0f : 0.0f;
            m = fmaxf(hm_m.z, fmaxf(hm_c.z, hm_p.z));
            res.z = (by && bx2 && v_cur.z >= REP_THR && v_cur.z == m) ? 1.0f : 0.0f;
            m = fmaxf(hm_m.w, fmaxf(hm_c.w, hm_p.w));
            res.w = (by && bx3 && v_cur.w >= REP_THR && v_cur.w == m) ? 1.0f : 0.0f;
        }

        *reinterpret_cast<float4*>(o + (size_t)y * W + x4) = res;

        hm_m = hm_c;
        hm_c = hm_p;
        v_cur = v_nxt;
    }
}

extern "C" void kernel_launch(void* const* d_in, const int* in_sizes, int n_in,
                              void* d_out, int out_size) {
    const float* in = (const float*)d_in[0];
    float* out = (float*)d_out;
    (void)in_sizes; (void)n_in; (void)out_size;

    dim3 block(32, 4);                 // 4 warps, each one column segment
    dim3 grid(16 / 4, H / ROWS, 8);    // (4 segment-groups, 64 row strips, 8 batch)
    nms_kernel<<<grid, block>>>(in, out);
}

// round 2
// speedup vs baseline: 1.0807x; 1.0807x over previous
#include <cuda_runtime.h>
#include <math_constants.h>

// NonMaxSuppression: 3x3 max-pool NMS mask on (8,1,2048,2048) fp32.
// out[y][x] = 1.0f iff in[y][x] == max3x3(in, y, x)  (pad -inf)
//             && in[y][x] >= 0.6f
//             && 10 <= y < H-10 && 10 <= x < W-10
//
// R2: software-pipelined row loads. Raw LDG.128 (+ predicated edge scalars)
// is issued one iteration before the dependent __shfl/hmax consume, and the
// loop is unrolled 4x so ptxas batches 4+ independent row loads -> MLP ~4-5
// per warp instead of 1. Output stores use __stcs (write-only stream,
// evict-first) to keep L2 for the input halo reuse.

#define H 2048
#define W 2048
#define ROWS 32
#define REP_THR 0.6f
#define BORDER 10

__device__ __forceinline__ float4 hmax4(float4 v, float l, float r) {
    float4 h;
    h.x = fmaxf(l,   fmaxf(v.x, v.y));
    h.y = fmaxf(v.x, fmaxf(v.y, v.z));
    h.z = fmaxf(v.y, fmaxf(v.z, v.w));
    h.w = fmaxf(v.z, fmaxf(v.w, r));
    return h;
}

struct Row {
    float4 v;   // 4 pixels
    float  l;   // left halo  (valid in lane 0 only)
    float  r;   // right halo (valid in lane 31 only)
};

__global__ __launch_bounds__(128, 8)
void nms_kernel(const float* __restrict__ in, float* __restrict__ out) {
    const int lane = threadIdx.x;                              // 0..31
    const int seg  = blockIdx.x * blockDim.y + threadIdx.y;    // 0..15
    const int b    = blockIdx.z;
    const int y0   = blockIdx.y * ROWS;

    const int x4 = seg * 128 + lane * 4;

    const float* img = in  + (size_t)b * H * W;
    float*       o   = out + (size_t)b * H * W;

    // Raw load: no shfl, no dependency on other lanes. Edge scalars are
    // predicated (lanes 0 / 31 only).
    auto load_raw = [&](int y) -> Row {
        Row p;
        int yy = y < 0 ? 0 : (y >= H ? H - 1 : y);
        const float* row = img + (size_t)yy * W;
        p.v = *reinterpret_cast<const float4*>(row + x4);
        p.l = (lane == 0  && x4 > 0)     ? row[x4 - 1] : -CUDART_INF_F;
        p.r = (lane == 31 && x4 + 4 < W) ? row[x4 + 4] : -CUDART_INF_F;
        return p;
    };

    // Consume: cross-lane halo exchange + horizontal 3-max. Runs one
    // iteration after the raw load so the LDG latency is already covered.
    auto consume = [&](const Row& p) -> float4 {
        float l = __shfl_up_sync(0xffffffffu,   p.v.w, 1);
        float r = __shfl_down_sync(0xffffffffu, p.v.x, 1);
        if (lane == 0)  l = p.l;
        if (lane == 31) r = p.r;
        return hmax4(p.v, l, r);
    };

    // Prologue: rows y0-1, y0 consumed immediately; row y0+1 left in flight.
    Row p_m = load_raw(y0 - 1);
    Row p_c = load_raw(y0);
    Row p_n = load_raw(y0 + 1);

    float4 hm_m  = consume(p_m);
    float4 hm_c  = consume(p_c);
    float4 v_cur = p_c.v;

    const bool bx0 = (x4 + 0 >= BORDER) && (x4 + 0 < W - BORDER);
    const bool bx1 = (x4 + 1 >= BORDER) && (x4 + 1 < W - BORDER);
    const bool bx2 = (x4 + 2 >= BORDER) && (x4 + 2 < W - BORDER);
    const bool bx3 = (x4 + 3 >= BORDER) && (x4 + 3 < W - BORDER);

    #pragma unroll 4
    for (int y = y0; y < y0 + ROWS; ++y) {
        // Issue next raw load first — independent of everything below.
        Row p_nn = load_raw(y + 2);

        // Consume the row loaded last iteration (latency already hidden).
        float4 hm_p = consume(p_n);

        const bool by = (y >= BORDER) && (y < H - BORDER);

        float4 res;
        {
            float m;
            m = fmaxf(hm_m.x, fmaxf(hm_c.x, hm_p.x));
            res.x = (by && bx0 && v_cur.x >= REP_THR && v_cur.x == m) ? 1.0f : 0.0f;
            m = fmaxf(hm_m.y, fmaxf(hm_c.y, hm_p.y));
            res.y = (by && bx1 && v_cur.y >= REP_THR && v_cur.y == m) ? 1.0f : 0.0f;
            m = fmaxf(hm_m.z, fmaxf(hm_c.z, hm_p.z));
            res.z = (by && bx2 && v_cur.z >= REP_THR && v_cur.z == m) ? 1.0f : 0.0f;
            m = fmaxf(hm_m.w, fmaxf(hm_c.w, hm_p.w));
            res.w = (by && bx3 && v_cur.w >= REP_THR && v_cur.w == m) ? 1.0f : 0.0f;
        }

        // Streaming store: output is never re-read, don't occupy L2.
        __stcs(reinterpret_cast<float4*>(o + (size_t)y * W + x4), res);

        hm_m  = hm_c;
        hm_c  = hm_p;
        v_cur = p_n.v;
        p_n   = p_nn;
    }
}

extern "C" void kernel_launch(void* const* d_in, const int* in_sizes, int n_in,
                              void* d_out, int out_size) {
    const float* in = (const float*)d_in[0];
    float* out = (float*)d_out;
    (void)in_sizes; (void)n_in; (void)out_size;

    dim3 block(32, 4);                 // 4 warps, each owns a 128-col segment
    dim3 grid(16 / 4, H / ROWS, 8);    // (segment groups, row strips, batch)
    nms_kernel<<<grid, block>>>(in, out);
}